// round 8
// baseline (speedup 1.0000x reference)
#include <cuda_runtime.h>
#include <cuda_bf16.h>
#include <cstdint>
#include <cstddef>

// ---------------------------------------------------------------------------
// BinaryConv2d forward:
//   x -> (x*rd_k+rd_b) -> sign -> 3x3 conv with (scaling[oc]*sign(w))
//     -> +pb0 -> PReLU -> +pb1 -> +x
// B=16, C=64, H=W=256. Output fp32 NCHW.
//
// Round 8:
//   K1: weights prep (grid slice) + binarize/bitpack x -> gPack (2 bit/elem).
//   K2: M=256 per CTA (full image row), ldmatrix.x4 fragment loads,
//       exact int8 mma.sync.m16n8k32 conv, fp32 epilogue + residual.
// ---------------------------------------------------------------------------

#define C_CH   64
#define IMG    256
#define HWSZ   (IMG*IMG)
#define KTOT   576              // 9 taps * 64 ic

// ---- K2 smem layout (bytes). ACT and EPI union (disjoint lifetimes). ------
#define ACT_PIX_STRIDE 80                     // 64 ic bytes padded to 80
#define ACT_ROW_STRIDE (258*ACT_PIX_STRIDE)   // 20640
#define EPI_PIX_STRIDE 65                     // words, padded from 64
#define SMEM_ACT  0                           // 3*20640 = 61920
#define SMEM_EPI  0                           // union: 256*65*4 = 66560
#define SMEM_B    66560
#define B_OC_STRIDE 592                       // 576 padded (148 words, mod32=20)
#define B_BYTES   (64*B_OC_STRIDE)            // 37888
#define SMEM_PAR  (SMEM_B + B_BYTES)          // 104448: 256 floats
#define SMEM_LUT  (SMEM_PAR + 1024)           // 105472: 256 uint32
#define SMEM_TOTAL (SMEM_LUT + 1024)          // 106496  (2 CTAs/SM)

static __device__ __align__(16) int8_t gW[64 * KTOT];   // [oc][tap*64+ic]
static __device__ float gScaling[C_CH];
// Packed signs: per pixel uint4 {pos lo32, pos hi32, neg lo32, neg hi32}.
static __device__ uint4 gPack[16 * IMG * IMG];          // 16.78 MB

// ---------------------------------------------------------------------------
// K1: grid (IMG, 17).  y<16: binarize+bitpack row (x=h, y=b), thread=w.
//                      y==16 && x<64: weight binarize + per-oc mean|w|.
// ---------------------------------------------------------------------------
__global__ void __launch_bounds__(256) pack_kernel(
    const float* __restrict__ x,
    const float* __restrict__ rdk,
    const float* __restrict__ rdb,
    const float* __restrict__ w)
{
    __shared__ float sk[64], so[64], red[256];
    const int tid = threadIdx.x;

    if (blockIdx.y == 16) {                    // ---- weight prep slice ----
        if (blockIdx.x >= 64) return;
        const int oc = blockIdx.x;
        float a = 0.f;
        for (int j = tid; j < 576; j += 256) {
            float v = w[oc * 576 + j];
            a += fabsf(v);
            int ic  = j / 9;
            int tap = j - ic * 9;
            gW[oc * KTOT + tap * 64 + ic] =
                (v > 0.f) ? (int8_t)1 : ((v < 0.f) ? (int8_t)-1 : (int8_t)0);
        }
        red[tid] = a;
        __syncthreads();
        for (int o = 128; o > 0; o >>= 1) {
            if (tid < o) red[tid] += red[tid + o];
            __syncthreads();
        }
        if (tid == 0) gScaling[oc] = red[0] * (1.0f / 576.0f);
        return;
    }

    const int h = blockIdx.x;
    const int b = blockIdx.y;
    if (tid < 64) { sk[tid] = rdk[tid]; so[tid] = rdb[tid]; }
    __syncthreads();

    const float* xp = x + (size_t)b * C_CH * HWSZ + (size_t)h * IMG + tid;
    uint32_t p0 = 0, p1 = 0, n0 = 0, n1 = 0;
    #pragma unroll
    for (int c = 0; c < 32; c++) {
        float a = xp[(size_t)c * HWSZ] * sk[c] + so[c];
        p0 |= (a > 0.f ? 1u : 0u) << c;
        n0 |= (a < 0.f ? 1u : 0u) << c;
    }
    #pragma unroll
    for (int c = 0; c < 32; c++) {
        float a = xp[(size_t)(c + 32) * HWSZ] * sk[c + 32] + so[c + 32];
        p1 |= (a > 0.f ? 1u : 0u) << c;
        n1 |= (a < 0.f ? 1u : 0u) << c;
    }
    gPack[((size_t)b * IMG + h) * IMG + tid] = make_uint4(p0, p1, n0, n1);
}

// ---------------------------------------------------------------------------
__device__ __forceinline__ void mma_s8(int32_t* c, uint32_t a0, uint32_t a1,
                                       uint32_t a2, uint32_t a3,
                                       uint32_t b0, uint32_t b1) {
    asm volatile(
        "mma.sync.aligned.m16n8k32.row.col.s32.s8.s8.s32 "
        "{%0,%1,%2,%3}, {%4,%5,%6,%7}, {%8,%9}, {%0,%1,%2,%3};"
        : "+r"(c[0]), "+r"(c[1]), "+r"(c[2]), "+r"(c[3])
        : "r"(a0), "r"(a1), "r"(a2), "r"(a3), "r"(b0), "r"(b1));
}

__device__ __forceinline__ void ldsm_x4(uint32_t* r, uint32_t addr) {
    asm volatile(
        "ldmatrix.sync.aligned.m8n8.x4.shared.b16 {%0,%1,%2,%3}, [%4];"
        : "=r"(r[0]), "=r"(r[1]), "=r"(r[2]), "=r"(r[3]) : "r"(addr));
}

// ---------------------------------------------------------------------------
// K2: conv. CTA = (h, b), M=256 (full row), N=64 oc, K=576. 8 warps.
// Warp w owns rows [32w, 32w+32): 2 m16 tiles. ldmatrix.x4 fragments.
// ---------------------------------------------------------------------------
__global__ void __launch_bounds__(256) binconv_kernel(
    const float* __restrict__ x,
    const float* __restrict__ pb0,
    const float* __restrict__ prw,
    const float* __restrict__ pb1,
    float* __restrict__ out)
{
    extern __shared__ __align__(128) char smem[];
    const int tid  = threadIdx.x;
    const int wid  = tid >> 5;
    const int lane = tid & 31;
    const int h    = blockIdx.x;
    const int b    = blockIdx.y;

    char* act = smem + SMEM_ACT;
    char* Bsm = smem + SMEM_B;
    int32_t* epi = reinterpret_cast<int32_t*>(smem + SMEM_EPI);
    float* par = reinterpret_cast<float*>(smem + SMEM_PAR);
    uint32_t* lut = reinterpret_cast<uint32_t*>(smem + SMEM_LUT);

    // ---- weights into smem ([oc][592] padded) ------------------------------
    {
        const uint32_t* src = reinterpret_cast<const uint32_t*>(gW);
        for (int i = tid; i < 64 * (KTOT / 4); i += 256) {
            int oc = i / (KTOT / 4);
            int wd = i - oc * (KTOT / 4);
            reinterpret_cast<uint32_t*>(Bsm + oc * B_OC_STRIDE)[wd] =
                src[oc * (KTOT / 4) + wd];
        }
    }
    // ---- epilogue params + nibble->byte4 LUT -------------------------------
    if (tid < 64) {
        par[tid]       = gScaling[tid];
        par[64 + tid]  = pb0[tid];
        par[128 + tid] = prw[tid];
        par[192 + tid] = pb1[tid];
    }
    {
        const uint32_t pos = tid & 0xFu, neg = tid >> 4;   // tid < 256
        uint32_t wv = 0;
        #pragma unroll
        for (int k = 0; k < 4; k++) {
            uint32_t byte = ((pos >> k) & 1u) ? 0x01u
                          : (((neg >> k) & 1u) ? 0xFFu : 0x00u);
            wv |= byte << (8 * k);
        }
        lut[tid] = wv;
    }
    __syncthreads();

    // ---- act halo: 3 rows x 258 cols; 1 uint4 load + LUT expand ------------
    for (int i = tid; i < 3 * 258; i += 256) {
        const int r   = i / 258;
        const int col = i - r * 258;
        const int ih  = h - 1 + r;
        const int iw  = col - 1;
        char* dst = act + r * ACT_ROW_STRIDE + col * ACT_PIX_STRIDE;
        if (ih >= 0 && ih < IMG && iw >= 0 && iw < IMG) {
            const uint4 pk = gPack[((size_t)b * IMG + ih) * IMG + iw];
            uint32_t wb[16];
            #pragma unroll
            for (int j = 0; j < 8; j++) {
                wb[j]     = lut[((pk.x >> (4 * j)) & 0xFu) |
                                (((pk.z >> (4 * j)) & 0xFu) << 4)];
                wb[j + 8] = lut[((pk.y >> (4 * j)) & 0xFu) |
                                (((pk.w >> (4 * j)) & 0xFu) << 4)];
            }
            #pragma unroll
            for (int q = 0; q < 4; q++)
                *reinterpret_cast<uint4*>(dst + q * 16) =
                    make_uint4(wb[4*q], wb[4*q+1], wb[4*q+2], wb[4*q+3]);
        } else {
            #pragma unroll
            for (int q = 0; q < 4; q++)
                *reinterpret_cast<uint4*>(dst + q * 16) =
                    make_uint4(0u, 0u, 0u, 0u);
        }
    }
    __syncthreads();

    // ---- MMA mainloop ------------------------------------------------------
    int32_t acc[2][8][4];
    #pragma unroll
    for (int mt = 0; mt < 2; mt++)
        #pragma unroll
        for (int nb = 0; nb < 8; nb++)
            #pragma unroll
            for (int i = 0; i < 4; i++) acc[mt][nb][i] = 0;

    const uint32_t actU = (uint32_t)__cvta_generic_to_shared(act);
    const uint32_t bU   = (uint32_t)__cvta_generic_to_shared(Bsm);
    const int rows0 = wid << 5;

    // ldmatrix lane-address bases.
    // A x4 (mt): mats = rows0..7/k0-15, rows8..15/k0-15, rows0..7/k16-31,
    //            rows8..15/k16-31 of the 16x32B fragment.
    const int sel  = lane >> 3;                  // 0..3
    const int r8   = (sel & 1) * 8;
    const int k16a = (sel >> 1) * 16;
    uint32_t baseA[2];
    #pragma unroll
    for (int mt = 0; mt < 2; mt++)
        baseA[mt] = actU + (rows0 + mt * 16 + r8 + (lane & 7)) * ACT_PIX_STRIDE
                  + k16a;
    // B x4 (p covers oc 16p..16p+15): lanes 0-7 oc+0..7/k0, 8-15 oc+0..7/k16,
    //                                 16-23 oc+8..15/k0, 24-31 oc+8..15/k16.
    const int ocOff = ((lane >> 4) & 1) * 8 + (lane & 7);
    const int k16b  = ((lane >> 3) & 1) * 16;
    uint32_t baseB[4];
    #pragma unroll
    for (int p = 0; p < 4; p++)
        baseB[p] = bU + (p * 16 + ocOff) * B_OC_STRIDE + k16b;

    #pragma unroll
    for (int tap = 0; tap < 9; tap++) {
        const int kh = tap / 3, kw = tap - 3 * kh;
        const uint32_t koffA = kh * ACT_ROW_STRIDE + kw * ACT_PIX_STRIDE;
        #pragma unroll
        for (int half = 0; half < 2; half++) {
            uint32_t A[2][4];
            #pragma unroll
            for (int mt = 0; mt < 2; mt++)
                ldsm_x4(A[mt], baseA[mt] + koffA + half * 32);
            #pragma unroll
            for (int p = 0; p < 4; p++) {
                uint32_t Bf[4];
                ldsm_x4(Bf, baseB[p] + tap * 64 + half * 32);
                #pragma unroll
                for (int mt = 0; mt < 2; mt++) {
                    mma_s8(acc[mt][2*p],   A[mt][0], A[mt][1], A[mt][2], A[mt][3],
                           Bf[0], Bf[1]);
                    mma_s8(acc[mt][2*p+1], A[mt][0], A[mt][1], A[mt][2], A[mt][3],
                           Bf[2], Bf[3]);
                }
            }
        }
    }

    // ---- EPI overlaps ACT: all warps finish reading act first --------------
    __syncthreads();

    {
        const int oc0 = 2 * (lane & 3);
        #pragma unroll
        for (int mt = 0; mt < 2; mt++) {
            const int mrow = rows0 + mt * 16 + (lane >> 2);
            #pragma unroll
            for (int nb = 0; nb < 8; nb++) {
                int oc = nb * 8 + oc0;
                epi[mrow * EPI_PIX_STRIDE + oc]           = acc[mt][nb][0];
                epi[mrow * EPI_PIX_STRIDE + oc + 1]       = acc[mt][nb][1];
                epi[(mrow + 8) * EPI_PIX_STRIDE + oc]     = acc[mt][nb][2];
                epi[(mrow + 8) * EPI_PIX_STRIDE + oc + 1] = acc[mt][nb][3];
            }
        }
    }
    __syncthreads();

    // ---- epilogue: scale/bias/prelu/bias + residual, coalesced stores ------
    const size_t base = (size_t)b * C_CH * HWSZ + (size_t)h * IMG;
    #pragma unroll 4
    for (int i = tid; i < 64 * IMG; i += 256) {
        int oc  = i >> 8;
        int pix = i & 255;
        float f = (float)epi[pix * EPI_PIX_STRIDE + oc];
        f = f * par[oc] + par[64 + oc];
        f = (f >= 0.f) ? f : (par[128 + oc] * f);
        f += par[192 + oc];
        size_t idx = base + (size_t)oc * HWSZ + pix;
        f += __ldg(x + idx);
        out[idx] = f;
    }
}

// ---------------------------------------------------------------------------
extern "C" void kernel_launch(void* const* d_in, const int* in_sizes, int n_in,
                              void* d_out, int out_size) {
    (void)in_sizes; (void)n_in; (void)out_size;
    const float* x     = (const float*)d_in[0];
    const float* rdk   = (const float*)d_in[1];
    const float* rdb   = (const float*)d_in[2];
    /* beta (d_in[3]) does not affect the STE forward pass */
    const float* convw = (const float*)d_in[4];
    const float* pb0   = (const float*)d_in[5];
    const float* prw   = (const float*)d_in[6];
    const float* pb1   = (const float*)d_in[7];
    float* out = (float*)d_out;

    pack_kernel<<<dim3(IMG, 17), 256>>>(x, rdk, rdb, convw);

    cudaFuncSetAttribute(binconv_kernel,
                         cudaFuncAttributeMaxDynamicSharedMemorySize, SMEM_TOTAL);
    binconv_kernel<<<dim3(IMG, 16), 256, SMEM_TOTAL>>>(x, pb0, prw, pb1, out);
}